// round 2
// baseline (speedup 1.0000x reference)
#include <cuda_runtime.h>
#include <cstdint>
#include <cstddef>

#define BATCH 4096
#define DIM   1024
#define TDICT 32768
#define TOPK  64

// ---------------- scratch (device globals: no runtime allocation allowed) ---
__device__ float g_xc[(size_t)BATCH * DIM];          // centered input, 16 MB
__device__ float g_acts[(size_t)BATCH * TDICT];      // relu(pre_acts), 512 MB
__device__ int   g_tidx[BATCH * TOPK];
__device__ float g_tval[BATCH * TOPK];

// ---------------- kernel 1: xc = x - b_dec ---------------------------------
__global__ void center_kernel(const float* __restrict__ x,
                              const float* __restrict__ b_dec) {
    int i = blockIdx.x * blockDim.x + threadIdx.x;   // over BATCH*DIM/4 float4
    float4 xv = reinterpret_cast<const float4*>(x)[i];
    float4 bv = reinterpret_cast<const float4*>(b_dec)[i & (DIM / 4 - 1)];
    xv.x -= bv.x; xv.y -= bv.y; xv.z -= bv.z; xv.w -= bv.w;
    reinterpret_cast<float4*>(g_xc)[i] = xv;
}

// ---------------- kernel 2: acts = relu(xc @ W_enc + b_enc) -----------------
// fp32 SGEMM, BM=BN=128, BK=16, 256 threads, 8x8 micro-tile per thread.
#define BM 128
#define BN 128
#define BK 16

__global__ __launch_bounds__(256, 1)
void sgemm_relu_kernel(const float* __restrict__ W, const float* __restrict__ bias) {
    __shared__ float As[BK][BM];
    __shared__ float Bs[BK][BN];

    const int tid = threadIdx.x;
    const int tx = tid & 15;          // 0..15 -> N
    const int ty = tid >> 4;          // 0..15 -> M
    const int m0 = blockIdx.y * BM;
    const int n0 = blockIdx.x * BN;

    // A-tile load map: 128 rows x 16 cols; thread -> (row=tid/2, col8=(tid&1)*8)
    const int ar = tid >> 1;
    const int ac = (tid & 1) * 8;
    // B-tile load map: 16 rows x 128 cols; thread -> (row=tid/16, col8=(tid&15)*8)
    const int br = tid >> 4;
    const int bc = (tid & 15) * 8;

    float acc[8][8];
#pragma unroll
    for (int i = 0; i < 8; i++)
#pragma unroll
        for (int j = 0; j < 8; j++) acc[i][j] = 0.f;

    const float* Ag = g_xc + (size_t)(m0 + ar) * DIM + ac;
    const float* Bg = W + (size_t)br * TDICT + n0 + bc;

    for (int k0 = 0; k0 < DIM; k0 += BK) {
        float4 a0 = *reinterpret_cast<const float4*>(Ag + k0);
        float4 a1 = *reinterpret_cast<const float4*>(Ag + k0 + 4);
        As[ac + 0][ar] = a0.x; As[ac + 1][ar] = a0.y;
        As[ac + 2][ar] = a0.z; As[ac + 3][ar] = a0.w;
        As[ac + 4][ar] = a1.x; As[ac + 5][ar] = a1.y;
        As[ac + 6][ar] = a1.z; As[ac + 7][ar] = a1.w;
        const float* bptr = Bg + (size_t)k0 * TDICT;
        *reinterpret_cast<float4*>(&Bs[br][bc])     = *reinterpret_cast<const float4*>(bptr);
        *reinterpret_cast<float4*>(&Bs[br][bc + 4]) = *reinterpret_cast<const float4*>(bptr + 4);
        __syncthreads();

#pragma unroll
        for (int kk = 0; kk < BK; kk++) {
            float a[8], b[8];
            *reinterpret_cast<float4*>(a)     = *reinterpret_cast<float4*>(&As[kk][ty * 8]);
            *reinterpret_cast<float4*>(a + 4) = *reinterpret_cast<float4*>(&As[kk][ty * 8 + 4]);
            *reinterpret_cast<float4*>(b)     = *reinterpret_cast<float4*>(&Bs[kk][tx * 8]);
            *reinterpret_cast<float4*>(b + 4) = *reinterpret_cast<float4*>(&Bs[kk][tx * 8 + 4]);
#pragma unroll
            for (int i = 0; i < 8; i++)
#pragma unroll
                for (int j = 0; j < 8; j++) acc[i][j] += a[i] * b[j];
        }
        __syncthreads();
    }

    float bv[8];
#pragma unroll
    for (int j = 0; j < 8; j++) bv[j] = bias[n0 + tx * 8 + j];

#pragma unroll
    for (int i = 0; i < 8; i++) {
        float* crow = g_acts + (size_t)(m0 + ty * 8 + i) * TDICT + n0 + tx * 8;
        float4 o0, o1;
        float v;
        v = acc[i][0] + bv[0]; o0.x = v > 0.f ? v : 0.f;
        v = acc[i][1] + bv[1]; o0.y = v > 0.f ? v : 0.f;
        v = acc[i][2] + bv[2]; o0.z = v > 0.f ? v : 0.f;
        v = acc[i][3] + bv[3]; o0.w = v > 0.f ? v : 0.f;
        v = acc[i][4] + bv[4]; o1.x = v > 0.f ? v : 0.f;
        v = acc[i][5] + bv[5]; o1.y = v > 0.f ? v : 0.f;
        v = acc[i][6] + bv[6]; o1.z = v > 0.f ? v : 0.f;
        v = acc[i][7] + bv[7]; o1.w = v > 0.f ? v : 0.f;
        *reinterpret_cast<float4*>(crow)     = o0;
        *reinterpret_cast<float4*>(crow + 4) = o1;
    }
}

// ---------------- kernel 3: per-row top-64 (radix select in SMEM) -----------
// Values are post-ReLU (>=0), so uint bit pattern order == float order.
// Tie-break matches jax.lax.top_k: strictly-greater taken, then lowest-index
// ties at the threshold value.
__global__ __launch_bounds__(256, 1)
void topk_kernel() {
    extern __shared__ unsigned int sv[];            // TDICT uints (128 KB)
    __shared__ unsigned int hist[256];
    __shared__ unsigned int sW1[8], sW2[8];
    __shared__ unsigned int s_pref, s_kneed;
    __shared__ int s_cgt, s_ceq;

    const int tid = threadIdx.x;
    const int row = blockIdx.x;
    const unsigned int* arow =
        reinterpret_cast<const unsigned int*>(g_acts + (size_t)row * TDICT);
    for (int i = tid; i < TDICT; i += 256) sv[i] = arow[i];

    unsigned int pref = 0, kneed = TOPK;
    for (int p = 24; p >= 0; p -= 8) {
        __syncthreads();
        hist[tid] = 0;
        __syncthreads();
        const unsigned int maskH = (p == 24) ? 0u : (0xFFFFFFFFu << (p + 8));
        for (int i = tid; i < TDICT; i += 256) {
            unsigned int v = sv[i];
            if ((v & maskH) == pref) atomicAdd(&hist[(v >> p) & 0xFFu], 1u);
        }
        __syncthreads();
        if (tid == 0) {
            unsigned int cum = 0;
            int b = 255;
            for (; b > 0; b--) {
                if (cum + hist[b] >= kneed) break;
                cum += hist[b];
            }
            s_pref = pref | ((unsigned int)b << p);
            s_kneed = kneed - cum;
        }
        __syncthreads();
        pref = s_pref;
        kneed = s_kneed;
    }

    const unsigned int thr = pref;       // bits of the 64th-largest value
    const int needeq = (int)kneed;       // how many ==thr to take
    const int ngt = TOPK - needeq;       // count of strictly-greater

    if (tid == 0) { s_cgt = 0; s_ceq = 0; }
    __syncthreads();

    const int lane = tid & 31, wid = tid >> 5;
    int*   oidx = g_tidx + row * TOPK;
    float* oval = g_tval + row * TOPK;

    for (int c0 = 0; c0 < TDICT; c0 += 256) {
        const unsigned int v = sv[c0 + tid];
        const bool pgt = v > thr;
        const bool peq = (v == thr);
        const unsigned int b1 = __ballot_sync(0xffffffffu, pgt);
        const unsigned int b2 = __ballot_sync(0xffffffffu, peq);
        if (lane == 0) { sW1[wid] = __popc(b1); sW2[wid] = __popc(b2); }
        __syncthreads();
        int off1 = 0, off2 = 0, t1 = 0, t2 = 0;
#pragma unroll
        for (int w = 0; w < 8; w++) {
            if (w < wid) { off1 += (int)sW1[w]; off2 += (int)sW2[w]; }
            t1 += (int)sW1[w]; t2 += (int)sW2[w];
        }
        const int base1 = s_cgt, base2 = s_ceq;
        const unsigned int lmask = (1u << lane) - 1u;
        const int r1 = base1 + off1 + __popc(b1 & lmask);
        const int r2 = base2 + off2 + __popc(b2 & lmask);
        if (pgt)               { oidx[r1] = c0 + tid;       oval[r1] = __uint_as_float(v); }
        if (peq && r2 < needeq){ oidx[ngt + r2] = c0 + tid; oval[ngt + r2] = __uint_as_float(v); }
        __syncthreads();
        if (tid == 0) { s_cgt = base1 + t1; s_ceq = base2 + t2; }
        __syncthreads();
        if (s_cgt >= ngt && s_ceq >= needeq) break;
    }
}

// ---------------- kernel 4: nested group decode -----------------------------
__global__ __launch_bounds__(256, 1)
void decode_kernel(const float* __restrict__ Wd, const float* __restrict__ bdec,
                   float* __restrict__ out) {
    __shared__ int   sidx[TOPK];
    __shared__ float sval[TOPK];
    const int row = blockIdx.x, tid = threadIdx.x;
    if (tid < TOPK) {
        sidx[tid] = g_tidx[row * TOPK + tid];
        sval[tid] = g_tval[row * TOPK + tid];
    }
    __syncthreads();

    float acc[4];
#pragma unroll
    for (int j = 0; j < 4; j++) acc[j] = bdec[tid + j * 256];

    const int bounds[4] = {0, 2048, 8192, TDICT};
#pragma unroll
    for (int g = 0; g < 3; g++) {
        for (int t = 0; t < TOPK; t++) {
            const int idx = sidx[t];
            if (idx >= bounds[g] && idx < bounds[g + 1]) {
                const float v = sval[t];
                const float* w = Wd + (size_t)idx * DIM;
#pragma unroll
                for (int j = 0; j < 4; j++) acc[j] += v * w[tid + j * 256];
            }
        }
        const size_t o = ((size_t)g * BATCH + row) * DIM;
#pragma unroll
        for (int j = 0; j < 4; j++) out[o + tid + j * 256] = acc[j];
    }
}

// ---------------- launch ----------------------------------------------------
extern "C" void kernel_launch(void* const* d_in, const int* in_sizes, int n_in,
                              void* d_out, int out_size) {
    const float* x     = (const float*)d_in[0];
    const float* W_enc = (const float*)d_in[1];
    const float* b_enc = (const float*)d_in[2];
    const float* W_dec = (const float*)d_in[3];
    const float* b_dec = (const float*)d_in[4];
    float* out = (float*)d_out;

    cudaFuncSetAttribute(topk_kernel,
                         cudaFuncAttributeMaxDynamicSharedMemorySize,
                         TDICT * (int)sizeof(unsigned int));

    center_kernel<<<(BATCH * DIM / 4) / 256, 256>>>(x, b_dec);

    dim3 grid(TDICT / BN, BATCH / BM);
    sgemm_relu_kernel<<<grid, 256>>>(W_enc, b_enc);

    topk_kernel<<<BATCH, 256, TDICT * sizeof(unsigned int)>>>();

    decode_kernel<<<BATCH, 256>>>(W_dec, b_dec, out);
}